// round 2
// baseline (speedup 1.0000x reference)
#include <cuda_runtime.h>

#define NTOT 50000
#define AANCH 32
#define DDIM 64
#define NG 3125          // NTOT/16 half-group count
#define BR 128
#define THREADS 128
#define XS_STRIDE 130
#define OS_STRIDE 65

// P' duplicated pairs: g_Cdup[a*128 + 2k {,+1}] = (1/32) * sum_d embeds[anchor[a],d]*W1[k,d]
__device__ __align__(16) float g_Cdup[AANCH * 2 * DDIM];
__device__ __align__(16) float g_E16[NG * DDIM];   // 16-row sums of embeds
__device__ __align__(16) float g_G[NG * DDIM];     // G[u,k] = (E16[u]+E16[u+1])/32 . W2^T + b

typedef unsigned long long u64;

__device__ __forceinline__ u64 pack2(float x, float y) {
    u64 r; asm("mov.b64 %0, {%1,%2};" : "=l"(r) : "f"(x), "f"(y)); return r;
}
__device__ __forceinline__ void unpack2(u64 v, float& x, float& y) {
    asm("mov.b64 {%0,%1}, %2;" : "=f"(x), "=f"(y) : "l"(v));
}
__device__ __forceinline__ u64 fma2(u64 a, u64 b, u64 c) {
    u64 d; asm("fma.rn.f32x2 %0, %1, %2, %3;" : "=l"(d) : "l"(a), "l"(b), "l"(c)); return d;
}

// ---------------------------------------------------------------------------
// k1: blocks [0, 782): E16 reduce (4 groups/block). blocks [782, 814): P'.
// ---------------------------------------------------------------------------
#define NB_E16 782
__global__ void k1_reduce_prep(const float* __restrict__ embeds,
                               const int* __restrict__ anchor,
                               const float* __restrict__ Wh)
{
    if (blockIdx.x < NB_E16) {
        int d = threadIdx.x & 63;
        int g = blockIdx.x * 4 + (threadIdx.x >> 6);
        if (g < NG) {
            const float* src = embeds + (size_t)(16 * g) * DDIM + d;
            float s = 0.f;
            #pragma unroll
            for (int j = 0; j < 16; j++) s += src[j * DDIM];
            g_E16[g * DDIM + d] = s;
        }
    } else {
        __shared__ float e[DDIM];
        int a = blockIdx.x - NB_E16;
        int t = threadIdx.x;
        if (t < DDIM) e[t] = embeds[(size_t)anchor[a] * DDIM + t];
        __syncthreads();
        if (t < DDIM) {
            const float* wrow = Wh + t * (2 * DDIM);   // W1[t][d] = Wh[t*128+d]
            float s = 0.f;
            #pragma unroll
            for (int d = 0; d < DDIM; d++) s += wrow[d] * e[d];
            s *= (1.0f / 32.0f);
            g_Cdup[a * 2 * DDIM + 2 * t]     = s;
            g_Cdup[a * 2 * DDIM + 2 * t + 1] = s;
        }
    }
}

// ---------------------------------------------------------------------------
// k2: G[u,k] = (1/32)*sum_d (E16[u,d]+E16[(u+1)%NG,d]) * W2[k,d] + b[k]
// 32 u per block, 256 threads, grid 98.
// ---------------------------------------------------------------------------
__global__ __launch_bounds__(256) void k2_G(const float* __restrict__ Wh,
                                            const float* __restrict__ bias)
{
    __shared__ float W2s[DDIM * 65];     // W2s[k*65+d]
    __shared__ float E32s[32 * 65];      // E32s[i*65+d]
    int tid = threadIdx.x;
    int u0 = blockIdx.x * 32;

    #pragma unroll
    for (int i = 0; i < 16; i++) {                       // 64*64 elems
        int idx = tid + i * 256;
        int k = idx >> 6, d = idx & 63;
        W2s[k * 65 + d] = Wh[k * (2 * DDIM) + DDIM + d]; // W2[k][d]
    }
    #pragma unroll
    for (int i = 0; i < 8; i++) {                        // 32*64 elems
        int idx = tid + i * 256;
        int iu = idx >> 6, d = idx & 63;
        int u = u0 + iu; if (u >= NG) u = NG - 1;
        int u2 = u + 1; if (u2 >= NG) u2 -= NG;
        E32s[iu * 65 + d] = g_E16[u * DDIM + d] + g_E16[u2 * DDIM + d];
    }
    __syncthreads();

    int iu = tid >> 3;            // 0..31
    int kbase = (tid & 7) * 8;    // 0,8,...,56
    int u = u0 + iu;
    float s[8];
    #pragma unroll
    for (int kk = 0; kk < 8; kk++) s[kk] = 0.f;
    #pragma unroll 8
    for (int d = 0; d < DDIM; d++) {
        float e = E32s[iu * 65 + d];
        #pragma unroll
        for (int kk = 0; kk < 8; kk++) s[kk] += e * W2s[(kbase + kk) * 65 + d];
    }
    if (u < NG) {
        #pragma unroll
        for (int kk = 0; kk < 8; kk++)
            g_G[u * DDIM + kbase + kk] = s[kk] * (1.0f / 32.0f) + bias[kbase + kk];
    }
}

// ---------------------------------------------------------------------------
// main: out[n,k] = sum_{a<32} dists[a,n]*P'[a,k] + G[(2n)%NG, k]
// ---------------------------------------------------------------------------
__global__ __launch_bounds__(THREADS) void main_kernel(
    const float* __restrict__ embeds,
    const float* __restrict__ dists,
    float* __restrict__ out)
{
    __shared__ float smem[BR * OS_STRIDE];               // 8320 floats = 33.3 KB
    float* Xs = smem;                                    // [32][130] = 4160
    float* Cd = smem + AANCH * XS_STRIDE;                // [32][128] = 4096
    const int tid = threadIdx.x;
    const int row0 = blockIdx.x * BR;

    const int cg = tid & 7;
    const int rg = tid >> 3;
    const int rbase = rg * 8;

    // ---- G gather: initialize accumulators (L2-resident G, b folded in)
    u64 acc[8][4];
    #pragma unroll
    for (int p = 0; p < 4; p++) {
        int n0 = row0 + rbase + 2 * p;
        int u_lo = (2 * n0) % NG;
        int u_hi = (2 * n0 + 2) % NG;
        const float* glo = g_G + u_lo * DDIM + cg;
        const float* ghi = g_G + u_hi * DDIM + cg;
        #pragma unroll
        for (int q = 0; q < 8; q++)
            acc[q][p] = pack2(__ldg(glo + 8 * q), __ldg(ghi + 8 * q));
    }

    // ---- stage P' dup pairs
    {
        const float4* src = (const float4*)g_Cdup;
        float4* dst = (float4*)Cd;
        #pragma unroll
        for (int i = 0; i < (AANCH * 2 * DDIM / 4) / THREADS; i++)   // 8
            dst[tid + i * THREADS] = src[tid + i * THREADS];
    }
    // ---- stage dists: Xs[a][r] = dists[a*N + row0+r]
    #pragma unroll
    for (int i = 0; i < (AANCH * BR) / THREADS; i++) {               // 32
        int idx = tid + i * THREADS;
        int a = idx >> 7, r = idx & 127;
        int row = row0 + r; if (row >= NTOT) row = NTOT - 1;
        Xs[a * XS_STRIDE + r] = dists[(size_t)a * NTOT + row];
    }
    __syncthreads();

    const float* xcol = Xs + rbase;
    const float* ccol = Cd + cg * 2;
    #pragma unroll 4
    for (int j = 0; j < AANCH; j++) {
        u64 xv[4];
        #pragma unroll
        for (int p = 0; p < 4; p++)
            xv[p] = *(const u64*)(xcol + j * XS_STRIDE + 2 * p);
        #pragma unroll
        for (int q = 0; q < 8; q++) {
            u64 cv = *(const u64*)(ccol + j * 2 * DDIM + 16 * q);
            #pragma unroll
            for (int p = 0; p < 4; p++)
                acc[q][p] = fma2(xv[p], cv, acc[q][p]);
        }
    }
    __syncthreads();

    // ---- transpose through shared for coalesced stores
    float* Os = smem;                                    // [128][65]
    #pragma unroll
    for (int q = 0; q < 8; q++) {
        int k = cg + 8 * q;
        #pragma unroll
        for (int p = 0; p < 4; p++) {
            float lo, hi; unpack2(acc[q][p], lo, hi);
            Os[(rbase + 2 * p) * OS_STRIDE + k] = lo;
            Os[(rbase + 2 * p + 1) * OS_STRIDE + k] = hi;
        }
    }
    __syncthreads();

    int rows_here = NTOT - row0; if (rows_here > BR) rows_here = BR;
    #pragma unroll
    for (int i = 0; i < (BR * DDIM) / THREADS; i++) {                // 64
        int idx = tid + i * THREADS;
        int r = idx >> 6, k = idx & 63;
        if (r < rows_here) out[(size_t)(row0 + r) * DDIM + k] = Os[r * OS_STRIDE + k];
    }
    (void)embeds;
}

// ---------------------------------------------------------------------------
extern "C" void kernel_launch(void* const* d_in, const int* in_sizes, int n_in,
                              void* d_out, int out_size)
{
    const float* embeds = (const float*)d_in[0];   // (N, D)
    const float* dists  = (const float*)d_in[1];   // (A, N)
    const int*   anchor = (const int*)d_in[2];     // (A,)
    const float* Wh     = (const float*)d_in[3];   // (D, 2D)
    const float* bias   = (const float*)d_in[4];   // (D,)
    float* out = (float*)d_out;
    (void)in_sizes; (void)n_in; (void)out_size;

    k1_reduce_prep<<<NB_E16 + AANCH, 256>>>(embeds, anchor, Wh);
    k2_G<<<(NG + 31) / 32, 256>>>(Wh, bias);
    main_kernel<<<(NTOT + BR - 1) / BR, THREADS>>>(embeds, dists, out);
}